// round 15
// baseline (speedup 1.0000x reference)
#include <cuda_runtime.h>
#include <cuda_bf16.h>
#include <math.h>

#define N0   4096
#define DD   320
#define DD2  640
#define KK0  3276
#define KK1  1965
#define NW   128

// ---- tf32 split-weight buffer (down-path only), float2 units ----
#define OFF_W0     0
#define OFF_DW0    102400
#define OFF_DW1    204800
#define TF32_TOT   307200

// ---- bf16 fragment buffer (up-path), uint32 units ----
#define FB_WB      0
#define FB_CATW0   102400
#define FB_CATW1   307200
#define FB_AGP0    512000
#define FB_AGP1    614400
#define FB_UW0     716800
#define FB_UW1     921600
#define FB_WE      1126400
#define FRAG_TOT   1331200
#define FRAG_SITES 665600

__device__ float2   s_Wsplit[TF32_TOT];
__device__ unsigned s_Wfrag [FRAG_TOT];
__device__ float    s_partial[2*N0*DD];
__device__ float    s_X0 [N0*DD];
__device__ float    s_X1d[N0*DD];
__device__ float    s_X2d[N0*DD];
__device__ float    s_Xb [N0*DD];
__device__ float    s_X1 [N0*DD];
__device__ float    s_X2 [N0*DD];
__device__ float    s_G  [N0*DD];
__device__ float    s_Xu1[N0*DD];
__device__ float    s_Xu0[N0*DD];
__device__ float    s_cat[N0*DD2];
__device__ unsigned s_bm [N0*NW];
__device__ float    s_h1 [N0];
__device__ float    s_e  [N0];
__device__ float    s_eh [N0];
__device__ float    s_sc [N0];
__device__ float    s_vals0[N0];
__device__ float    s_vals1[N0];
__device__ int      s_idx0[N0];
__device__ int      s_idx1[N0];
__device__ int      s_inv [N0];
__device__ float    s_biasGS[2*DD];

__device__ __forceinline__ unsigned cvt_tf32(float x) {
    unsigned r;
    asm("cvt.rna.tf32.f32 %0, %1;" : "=r"(r) : "f"(x));
    return r;
}
__device__ __forceinline__ float2 make_split(float x) {
    unsigned hi = cvt_tf32(x);
    float hf = __uint_as_float(hi);
    unsigned lo = cvt_tf32(x - hf);
    return make_float2(hf, __uint_as_float(lo));
}

__device__ __forceinline__ void mma8(float* d, const unsigned* a, const unsigned* b) {
    asm volatile(
        "mma.sync.aligned.m16n8k8.row.col.f32.tf32.tf32.f32 "
        "{%0,%1,%2,%3}, {%4,%5,%6,%7}, {%8,%9}, {%0,%1,%2,%3};"
        : "+f"(d[0]), "+f"(d[1]), "+f"(d[2]), "+f"(d[3])
        : "r"(a[0]), "r"(a[1]), "r"(a[2]), "r"(a[3]), "r"(b[0]), "r"(b[1]));
}

__device__ __forceinline__ void mma16(float* d, const unsigned* a, unsigned b0, unsigned b1) {
    asm volatile(
        "mma.sync.aligned.m16n8k16.row.col.f32.bf16.bf16.f32 "
        "{%0,%1,%2,%3}, {%4,%5,%6,%7}, {%8,%9}, {%0,%1,%2,%3};"
        : "+f"(d[0]), "+f"(d[1]), "+f"(d[2]), "+f"(d[3])
        : "r"(a[0]), "r"(a[1]), "r"(a[2]), "r"(a[3]), "r"(b0), "r"(b1));
}

__device__ __forceinline__ void cpa16(unsigned dst, const void* src, int nbytes) {
    asm volatile("cp.async.cg.shared.global [%0], [%1], 16, %2;"
                 :: "r"(dst), "l"(src), "r"(nbytes));
}

__device__ __forceinline__ unsigned split_bf2(float2 v, unsigned* lo) {
    __nv_bfloat162 h = __floats2bfloat162_rn(v.x, v.y);
    float2 hf = __bfloat1622float2(h);
    __nv_bfloat162 l = __floats2bfloat162_rn(v.x - hf.x, v.y - hf.y);
    *lo = *reinterpret_cast<unsigned*>(&l);
    return *reinterpret_cast<unsigned*>(&h);
}

// ---------------------------------------------------------------------------
// tf32 split + 64-col permutation (down-path weights) + fused bias sum tail
// ---------------------------------------------------------------------------
__global__ void prep_tf32(const float* __restrict__ W0,
                          const float* __restrict__ dW,
                          float2* __restrict__ out,
                          const float* __restrict__ bg,
                          const float* __restrict__ bs,
                          float* __restrict__ biasGS)
{
    int gid = blockIdx.x * blockDim.x + threadIdx.x;
    if (gid >= TF32_TOT) {
        int b = gid - TF32_TOT;
        if (b < 2 * DD) biasGS[b] = bg[b] + bs[b];
        return;
    }
    float x = (gid < 102400) ? W0[gid] : dW[gid - 102400];
    int col = gid % DD;
    int pcol = (col & ~63) | ((col & 7) << 3) | ((col >> 3) & 7);
    out[gid - col + pcol] = make_split(x);
}

// ---------------------------------------------------------------------------
// bf16 split + fragment-major packing (up-path weights)
// ---------------------------------------------------------------------------
__global__ void prep_frag(const float* __restrict__ Wb,
                          const float* __restrict__ agWg,
                          const float* __restrict__ agWs,
                          const float* __restrict__ agWp,
                          const float* __restrict__ uW,
                          const float* __restrict__ We,
                          unsigned* __restrict__ out)
{
    int gid = blockIdx.x * blockDim.x + threadIdx.x;
    if (gid >= FRAG_SITES) return;
    int s = gid;
    const float* src = nullptr;
    long fb = 0;
    int catL = -1;
    if (s < 51200)                    { src = Wb;             fb = FB_WB;    }
    else if ((s -= 51200) < 102400)   { catL = 0;             fb = FB_CATW0; }
    else if ((s -= 102400) < 102400)  { catL = 1;             fb = FB_CATW1; }
    else if ((s -= 102400) < 51200)   { src = agWp;           fb = FB_AGP0;  }
    else if ((s -= 51200) < 51200)    { src = agWp + 102400;  fb = FB_AGP1;  }
    else if ((s -= 51200) < 102400)   { src = uW;             fb = FB_UW0;   }
    else if ((s -= 102400) < 102400)  { src = uW + 204800;    fb = FB_UW1;   }
    else { s -= 102400;                 src = We;             fb = FB_WE;    }

    int block = s >> 9;
    int r = s & 511;
    int tg = r >> 7, g = (r >> 4) & 7, nt = (r >> 1) & 7, reg = r & 1;
    int kb = block / 5, cbi = block % 5;
    int k0 = kb * 16 + tg * 2 + reg * 8;
    int col = cbi * 64 + nt * 8 + g;
    float x0, x1;
    if (catL >= 0) {
        const float* g0 = agWg + catL * 102400;
        const float* s0 = agWs + catL * 102400;
        x0 = (k0 < 320) ? g0[k0 * 320 + col] : s0[(k0 - 320) * 320 + col];
        x1 = (k0 + 1 < 320) ? g0[(k0 + 1) * 320 + col] : s0[(k0 + 1 - 320) * 320 + col];
    } else {
        x0 = src[(size_t)k0 * 320 + col];
        x1 = src[(size_t)(k0 + 1) * 320 + col];
    }
    __nv_bfloat162 h = __floats2bfloat162_rn(x0, x1);
    float2 hf = __bfloat1622float2(h);
    __nv_bfloat162 l = __floats2bfloat162_rn(x0 - hf.x, x1 - hf.y);
    int q = nt * 2 + reg;
    int idx = (q >> 2) * 128 + (g * 4 + tg) * 4 + (q & 3);
    unsigned* blk = out + fb + (size_t)block * 1024;
    blk[idx]       = *reinterpret_cast<unsigned*>(&h);
    blk[512 + idx] = *reinterpret_cast<unsigned*>(&l);
}

__global__ void mask_build(const float* __restrict__ A, unsigned* __restrict__ bm) {
    int gid = blockIdx.x * blockDim.x + threadIdx.x;
    float v = A[gid];
    unsigned b = __ballot_sync(0xffffffffu, v != 0.0f);
    if ((threadIdx.x & 31) == 0) bm[gid >> 5] = b;
}

// ---------------------------------------------------------------------------
// tf32x3 GEMM (down path), 2-stage pipeline
// ---------------------------------------------------------------------------
#define AP_   36
#define BP_   66
#define GSMEM (2*64*AP_*4 + 2*32*BP_*8)

__global__ __launch_bounds__(128) void mm3t_kernel(
    int M, int N, int kslice,
    const float* __restrict__ A, int lda,
    const float2* __restrict__ B, int ldb,
    float* __restrict__ P)
{
    extern __shared__ float dsm[];
    float*  As = dsm;
    float2* Bs = (float2*)(dsm + 2 * 64 * AP_);

    const int tid  = threadIdx.x;
    const int wid  = tid >> 5;
    const int lane = tid & 31;
    const int g    = lane >> 2;
    const int tg   = lane & 3;

    const int row0  = blockIdx.y * 64;
    const int col0  = blockIdx.x * 64;
    const int kbase = blockIdx.z * kslice;
    const int rb    = wid * 16;

    unsigned aBase = (unsigned)__cvta_generic_to_shared(As);
    unsigned bBase = (unsigned)__cvta_generic_to_shared(Bs);

    float acc[8][4];
#pragma unroll
    for (int nt = 0; nt < 8; nt++) {
        acc[nt][0] = 0.f; acc[nt][1] = 0.f; acc[nt][2] = 0.f; acc[nt][3] = 0.f;
    }

    const int ktiles = kslice / 32;

    auto stage = [&](int kt, int s) {
        const int k0 = kbase + kt * 32;
#pragma unroll
        for (int i = 0; i < 4; i++) {
            int idx = i * 128 + tid;
            int r = idx >> 3, c4 = idx & 7;
            int gr = row0 + r;
            int nb = (gr < M) ? 16 : 0;
            int grc = gr < M ? gr : (M - 1);
            cpa16(aBase + (unsigned)(((s * 64 + r) * AP_ + c4 * 4) * 4),
                  A + (size_t)grc * lda + k0 + c4 * 4, nb);
        }
#pragma unroll
        for (int i = 0; i < 8; i++) {
            int idx = i * 128 + tid;
            int kr = idx >> 5, c2 = (idx & 31) * 2;
            cpa16(bBase + (unsigned)(((s * 32 + kr) * BP_ + c2) * 8),
                  B + (size_t)(k0 + kr) * ldb + col0 + c2, 16);
        }
        asm volatile("cp.async.commit_group;");
    };

    stage(0, 0);

    for (int kt = 0; kt < ktiles; kt++) {
        asm volatile("cp.async.wait_group 0;");
        __syncthreads();
        if (kt + 1 < ktiles) stage(kt + 1, (kt + 1) & 1);

        const int buf = kt & 1;
        const float*  Ab = As + buf * 64 * AP_;
        const float2* Bb = Bs + buf * 32 * BP_;

#pragma unroll
        for (int kk = 0; kk < 4; kk++) {
            const int kc = kk * 8;
            unsigned ahi[4], alo[4];
            {
                float x0 = Ab[(rb + g) * AP_ + kc + tg];
                float x1 = Ab[(rb + g + 8) * AP_ + kc + tg];
                float x2 = Ab[(rb + g) * AP_ + kc + tg + 4];
                float x3 = Ab[(rb + g + 8) * AP_ + kc + tg + 4];
                ahi[0] = cvt_tf32(x0); alo[0] = cvt_tf32(x0 - __uint_as_float(ahi[0]));
                ahi[1] = cvt_tf32(x1); alo[1] = cvt_tf32(x1 - __uint_as_float(ahi[1]));
                ahi[2] = cvt_tf32(x2); alo[2] = cvt_tf32(x2 - __uint_as_float(ahi[2]));
                ahi[3] = cvt_tf32(x3); alo[3] = cvt_tf32(x3 - __uint_as_float(ahi[3]));
            }
            const float4* rL = reinterpret_cast<const float4*>(Bb + (kc + tg) * BP_ + g * 8);
            const float4* rH = reinterpret_cast<const float4*>(Bb + (kc + tg + 4) * BP_ + g * 8);
            float4 Ls[4] = {rL[0], rL[1], rL[2], rL[3]};
            float4 Hs[4] = {rH[0], rH[1], rH[2], rH[3]};
#pragma unroll
            for (int nt = 0; nt < 8; nt++) {
                float4 l = Ls[nt >> 1], h = Hs[nt >> 1];
                float lx = (nt & 1) ? l.z : l.x;
                float ly = (nt & 1) ? l.w : l.y;
                float hx = (nt & 1) ? h.z : h.x;
                float hy = (nt & 1) ? h.w : h.y;
                unsigned bhi[2] = { __float_as_uint(lx), __float_as_uint(hx) };
                unsigned blo[2] = { __float_as_uint(ly), __float_as_uint(hy) };
                mma8(acc[nt], ahi, bhi);
                mma8(acc[nt], ahi, blo);
                mma8(acc[nt], alo, bhi);
            }
        }
        __syncthreads();
    }

    float* Pp = P + (size_t)blockIdx.z * M * N;
#pragma unroll
    for (int nt = 0; nt < 8; nt++) {
        const int col = col0 + nt * 8 + tg * 2;
#pragma unroll
        for (int h = 0; h < 2; h++) {
            const int r = row0 + rb + g + h * 8;
            if (r >= M) continue;
            *reinterpret_cast<float2*>(Pp + (size_t)r * N + col) =
                make_float2(acc[nt][h * 2 + 0], acc[nt][h * 2 + 1]);
        }
    }
}

// ---------------------------------------------------------------------------
// bf16x3 GEMM (up path), 3-stage cp.async pipeline
// ---------------------------------------------------------------------------
#define GS_BF (3*64*AP_*4 + 3*2048*4)

__global__ __launch_bounds__(128) void mmbf_kernel(
    int M, int N, int kslice,
    const float* __restrict__ A, int lda,
    const unsigned* __restrict__ Bf,
    float* __restrict__ P)
{
    extern __shared__ float dsm[];
    float*    As = dsm;                              // [3][64][AP_]
    unsigned* Bs = (unsigned*)(dsm + 3 * 64 * AP_);  // [3][2048]

    const int tid  = threadIdx.x;
    const int wid  = tid >> 5;
    const int lane = tid & 31;
    const int g    = lane >> 2;
    const int tg   = lane & 3;

    const int row0  = blockIdx.y * 64;
    const int col0  = blockIdx.x * 64;
    const int kbase = blockIdx.z * kslice;
    const int rb    = wid * 16;

    unsigned aBase = (unsigned)__cvta_generic_to_shared(As);
    unsigned bBase = (unsigned)__cvta_generic_to_shared(Bs);

    float acc[8][4];
#pragma unroll
    for (int nt = 0; nt < 8; nt++) {
        acc[nt][0] = 0.f; acc[nt][1] = 0.f; acc[nt][2] = 0.f; acc[nt][3] = 0.f;
    }

    const int ktiles = kslice / 32;

    auto stage = [&](int kt, int s) {
        const int k0 = kbase + kt * 32;
#pragma unroll
        for (int i = 0; i < 4; i++) {
            int idx = i * 128 + tid;
            int r = idx >> 3, c4 = idx & 7;
            int gr = row0 + r;
            int nb = (gr < M) ? 16 : 0;
            int grc = gr < M ? gr : (M - 1);
            cpa16(aBase + (unsigned)(((s * 64 + r) * AP_ + c4 * 4) * 4),
                  A + (size_t)grc * lda + k0 + c4 * 4, nb);
        }
        const int kb0 = k0 >> 4;
#pragma unroll
        for (int i = 0; i < 4; i++) {
            int c = i * 128 + tid;
            int sub = c >> 8, i16 = c & 255;
            const unsigned* src = Bf + ((size_t)(kb0 + sub) * 5 + blockIdx.x) * 1024 + i16 * 4;
            cpa16(bBase + (unsigned)((s * 2048 + sub * 1024 + i16 * 4) * 4), src, 16);
        }
        asm volatile("cp.async.commit_group;");
    };

    stage(0, 0);
    if (ktiles > 1) stage(1, 1);

    for (int kt = 0; kt < ktiles; kt++) {
        if (kt + 2 <= ktiles) {
            asm volatile("cp.async.wait_group 1;");
        } else {
            asm volatile("cp.async.wait_group 0;");
        }
        __syncthreads();
        if (kt + 2 < ktiles) stage(kt + 2, (kt + 2) % 3);

        const int buf = kt % 3;
        const float* Ab = As + buf * 64 * AP_;

#pragma unroll
        for (int sub = 0; sub < 2; sub++) {
            const unsigned* Bb = Bs + buf * 2048 + sub * 1024;
            float2 p0 = *reinterpret_cast<const float2*>(&Ab[(rb + g) * AP_ + sub * 16 + tg * 2]);
            float2 p1 = *reinterpret_cast<const float2*>(&Ab[(rb + g + 8) * AP_ + sub * 16 + tg * 2]);
            float2 p2 = *reinterpret_cast<const float2*>(&Ab[(rb + g) * AP_ + sub * 16 + tg * 2 + 8]);
            float2 p3 = *reinterpret_cast<const float2*>(&Ab[(rb + g + 8) * AP_ + sub * 16 + tg * 2 + 8]);
            unsigned ahi[4], alo[4];
            ahi[0] = split_bf2(p0, &alo[0]);
            ahi[1] = split_bf2(p1, &alo[1]);
            ahi[2] = split_bf2(p2, &alo[2]);
            ahi[3] = split_bf2(p3, &alo[3]);
            const uint4* bh4 = reinterpret_cast<const uint4*>(Bb + lane * 4);
            const uint4* bl4 = reinterpret_cast<const uint4*>(Bb + 512 + lane * 4);
            uint4 bh[4], bl[4];
#pragma unroll
            for (int j = 0; j < 4; j++) { bh[j] = bh4[j * 32]; bl[j] = bl4[j * 32]; }
#pragma unroll
            for (int nt = 0; nt < 8; nt++) {
                uint4 h = bh[nt >> 1], l = bl[nt >> 1];
                unsigned h0 = (nt & 1) ? h.z : h.x;
                unsigned h1 = (nt & 1) ? h.w : h.y;
                unsigned l0 = (nt & 1) ? l.z : l.x;
                unsigned l1 = (nt & 1) ? l.w : l.y;
                mma16(acc[nt], ahi, h0, h1);
                mma16(acc[nt], ahi, l0, l1);
                mma16(acc[nt], alo, h0, h1);
            }
        }
        __syncthreads();
    }

    float* Pp = P + (size_t)blockIdx.z * M * N;
#pragma unroll
    for (int nt = 0; nt < 8; nt++) {
        const int col = col0 + nt * 8 + tg * 2;
#pragma unroll
        for (int h = 0; h < 2; h++) {
            const int r = row0 + rb + g + h * 8;
            if (r >= M) continue;
            *reinterpret_cast<float2*>(Pp + (size_t)r * N + col) =
                make_float2(acc[nt][h * 2 + 0], acc[nt][h * 2 + 1]);
        }
    }
}

// C = act(P0 + P1 + bias) (+res after act)
__global__ void finish_kernel(int M, int N,
                              const float* __restrict__ P,
                              const float* __restrict__ bias,
                              float* __restrict__ C, int ldc,
                              const float* __restrict__ res, int ldres,
                              int act)
{
    int gid = blockIdx.x * blockDim.x + threadIdx.x;
    int total = (M * N) >> 2;
    if (gid >= total) return;
    int nq = N >> 2;
    int r = gid / nq;
    int c = (gid - r * nq) << 2;

    float4 p0 = reinterpret_cast<const float4*>(P)[gid];
    float4 p1 = reinterpret_cast<const float4*>(P + (size_t)M * N)[gid];
    float4 bv = *reinterpret_cast<const float4*>(bias + c);
    float v0 = p0.x + p1.x + bv.x;
    float v1 = p0.y + p1.y + bv.y;
    float v2 = p0.z + p1.z + bv.z;
    float v3 = p0.w + p1.w + bv.w;
    if (act == 1) {
        v0 = fmaxf(v0, 0.f); v1 = fmaxf(v1, 0.f);
        v2 = fmaxf(v2, 0.f); v3 = fmaxf(v3, 0.f);
    } else if (act == 2) {
        v0 = 1.f / (1.f + expf(-v0)); v1 = 1.f / (1.f + expf(-v1));
        v2 = 1.f / (1.f + expf(-v2)); v3 = 1.f / (1.f + expf(-v3));
    }
    if (res) {
        const float4 rv = *reinterpret_cast<const float4*>(res + (size_t)r * ldres + c);
        v0 += rv.x; v1 += rv.y; v2 += rv.z; v3 += rv.w;
    }
    *reinterpret_cast<float4*>(C + (size_t)r * ldc + c) = make_float4(v0, v1, v2, v3);
}

__global__ void gemv_score(int M, const float* __restrict__ X,
                           const float* __restrict__ w,
                           const float* __restrict__ pwb,
                           const float* __restrict__ pb,
                           const float* __restrict__ phi0,
                           float* __restrict__ h1,
                           float* __restrict__ e, float* __restrict__ eh)
{
    int warp = (blockIdx.x * blockDim.x + threadIdx.x) >> 5;
    int lane = threadIdx.x & 31;
    if (warp >= M) return;
    const float* xr = X + (size_t)warp * DD;
    float s = 0.f;
    for (int k = lane; k < DD; k += 32) s += xr[k] * w[k];
#pragma unroll
    for (int o = 16; o > 0; o >>= 1) s += __shfl_down_sync(0xffffffffu, s, o);
    if (lane == 0) {
        float h = s + pwb[0] + pb[0];
        float ex = expf(phi0[0] * h);
        h1[warp] = h;
        e[warp] = ex;
        eh[warp] = ex * h;
    }
}

__global__ void agg_l0(const unsigned* __restrict__ bm,
                       const float* __restrict__ e,
                       const float* __restrict__ eh,
                       float* __restrict__ scores)
{
    int r = blockIdx.x;
    int t = threadIdx.x;
    unsigned w = bm[r * NW + t];
    if ((r >> 5) == t) w |= (1u << (r & 31));
    float se = 0.f, sh = 0.f;
    while (w) {
        int b = __ffs(w) - 1;
        w &= w - 1;
        int j = t * 32 + b;
        se += e[j];
        sh += eh[j];
    }
    __shared__ float r1[128], r2[128];
    r1[t] = se; r2[t] = sh;
    __syncthreads();
    for (int o = 64; o > 0; o >>= 1) {
        if (t < o) { r1[t] += r1[t + o]; r2[t] += r2[t + o]; }
        __syncthreads();
    }
    if (t == 0) {
        float agg = (r2[0] / r1[0]) * 0.01f;
        scores[r] = 1.f / (1.f + expf(-agg));
    }
}

__global__ void agg_l1(const unsigned* __restrict__ bm,
                       const int* __restrict__ idx0, int n1,
                       const float* __restrict__ e,
                       const float* __restrict__ eh,
                       float* __restrict__ scores)
{
    __shared__ unsigned rowbits[NW];
    int r = blockIdx.x;
    int t = threadIdx.x;
    int orig = idx0[r];
    if (t < NW) rowbits[t] = bm[orig * NW + t];
    __syncthreads();
    float se = 0.f, sh = 0.f;
    for (int j = t; j < n1; j += 256) {
        int c = idx0[j];
        bool in = (rowbits[c >> 5] >> (c & 31)) & 1u;
        if (j == r) in = true;
        if (in) { se += e[j]; sh += eh[j]; }
    }
    __shared__ float r1[256], r2[256];
    r1[t] = se; r2[t] = sh;
    __syncthreads();
    for (int o = 128; o > 0; o >>= 1) {
        if (t < o) { r1[t] += r1[t + o]; r2[t] += r2[t + o]; }
        __syncthreads();
    }
    if (t == 0) {
        float agg = (r2[0] / r1[0]) * 0.01f;
        scores[r] = 1.f / (1.f + expf(-agg));
    }
}

__global__ void topk_rank(const float* __restrict__ s, int n, int kk,
                          int* __restrict__ idx, float* __restrict__ vals)
{
    __shared__ float buf[256];
    int i = blockIdx.x * blockDim.x + threadIdx.x;
    float si = (i < n) ? s[i] : 0.f;
    int rank = 0;
    for (int base = 0; base < n; base += 256) {
        int j = base + threadIdx.x;
        buf[threadIdx.x] = (j < n) ? s[j] : -3.0e38f;
        __syncthreads();
        int lim = min(256, n - base);
        for (int t = 0; t < lim; t++) {
            float sj = buf[t];
            int j2 = base + t;
            if (sj > si || (sj == si && j2 < i)) rank++;
        }
        __syncthreads();
    }
    if (i < n && rank < kk) { idx[rank] = i; vals[rank] = si; }
}

__global__ void pool_gather(const float* __restrict__ src,
                            const int* __restrict__ idx,
                            const float* __restrict__ vals,
                            int rows, float* __restrict__ dst)
{
    int gid = blockIdx.x * blockDim.x + threadIdx.x;
    if (gid >= rows * DD) return;
    int r = gid / DD, c = gid % DD;
    dst[gid] = src[(size_t)idx[r] * DD + c] * vals[r];
}

// inv[idx[i]] = (tag<<24) | i  (validity by tag; deterministic replays make
// stale same-tag entries harmless: the same set is rewritten each replay)
__global__ void inv_tag(int* __restrict__ inv, const int* __restrict__ idx,
                        int kk, int tag) {
    int i = blockIdx.x * blockDim.x + threadIdx.x;
    if (i < kk) inv[idx[i]] = (tag << 24) | i;
}

__global__ void cat_fill(float* __restrict__ cat,
                         const int* __restrict__ inv,
                         const float* __restrict__ top,
                         const float* __restrict__ down, int rows, int tag)
{
    int gid = blockIdx.x * blockDim.x + threadIdx.x;
    if (gid >= rows * DD) return;
    int r = gid / DD, c = gid % DD;
    int iv = inv[r];
    bool valid = (iv >> 24) == tag;
    int top_r = iv & 0xFFFFFF;
    cat[(size_t)r * DD2 + c] = valid ? top[(size_t)top_r * DD + c] : 0.f;
    cat[(size_t)r * DD2 + DD + c] = down[gid];
}

__global__ void head_fill(float* __restrict__ cat,
                          const float* __restrict__ a,
                          const float* __restrict__ b, int rows)
{
    int gid = blockIdx.x * blockDim.x + threadIdx.x;
    if (gid >= rows * DD) return;
    int r = gid / DD, c = gid % DD;
    cat[(size_t)r * DD2 + c] = a[gid];
    cat[(size_t)r * DD2 + DD + c] = b[gid];
}

extern "C" void kernel_launch(void* const* d_in, const int* in_sizes, int n_in,
                              void* d_out, int out_size)
{
    const float* A     = (const float*)d_in[0];
    const float* Xin   = (const float*)d_in[1];
    const float* W0    = (const float*)d_in[2];
    const float* b0    = (const float*)d_in[3];
    const float* Wb    = (const float*)d_in[4];
    const float* bb    = (const float*)d_in[5];
    const float* We    = (const float*)d_in[6];
    const float* be    = (const float*)d_in[7];
    const float* dW    = (const float*)d_in[8];
    const float* db    = (const float*)d_in[9];
    const float* uW    = (const float*)d_in[10];
    const float* ub    = (const float*)d_in[11];
    const float* pW    = (const float*)d_in[12];
    const float* pwb   = (const float*)d_in[13];
    const float* pb    = (const float*)d_in[14];
    const float* phi   = (const float*)d_in[15];
    const float* agWg  = (const float*)d_in[16];
    const float* agbg  = (const float*)d_in[17];
    const float* agWs  = (const float*)d_in[18];
    const float* agbs  = (const float*)d_in[19];
    const float* agWp  = (const float*)d_in[20];
    const float* agbp  = (const float*)d_in[21];

    float *part, *X0, *X1d, *X2d, *Xb, *X1, *X2, *G, *Xu1, *Xu0, *cat;
    float *h1, *e, *eh, *sc, *vals0, *vals1, *biasGS;
    float2* Ws;
    unsigned *Fr, *bm;
    int *idx0, *idx1, *inv;
    cudaGetSymbolAddress((void**)&Ws,   s_Wsplit);
    cudaGetSymbolAddress((void**)&Fr,   s_Wfrag);
    cudaGetSymbolAddress((void**)&part, s_partial);
    cudaGetSymbolAddress((void**)&X0,  s_X0);
    cudaGetSymbolAddress((void**)&X1d, s_X1d);
    cudaGetSymbolAddress((void**)&X2d, s_X2d);
    cudaGetSymbolAddress((void**)&Xb,  s_Xb);
    cudaGetSymbolAddress((void**)&X1,  s_X1);
    cudaGetSymbolAddress((void**)&X2,  s_X2);
    cudaGetSymbolAddress((void**)&G,   s_G);
    cudaGetSymbolAddress((void**)&Xu1, s_Xu1);
    cudaGetSymbolAddress((void**)&Xu0, s_Xu0);
    cudaGetSymbolAddress((void**)&cat, s_cat);
    cudaGetSymbolAddress((void**)&bm,  s_bm);
    cudaGetSymbolAddress((void**)&h1,  s_h1);
    cudaGetSymbolAddress((void**)&e,   s_e);
    cudaGetSymbolAddress((void**)&eh,  s_eh);
    cudaGetSymbolAddress((void**)&sc,  s_sc);
    cudaGetSymbolAddress((void**)&vals0, s_vals0);
    cudaGetSymbolAddress((void**)&vals1, s_vals1);
    cudaGetSymbolAddress((void**)&idx0, s_idx0);
    cudaGetSymbolAddress((void**)&idx1, s_idx1);
    cudaGetSymbolAddress((void**)&inv,  s_inv);
    cudaGetSymbolAddress((void**)&biasGS, s_biasGS);

    cudaFuncSetAttribute(mm3t_kernel,
                         cudaFuncAttributeMaxDynamicSharedMemorySize, GSMEM);
    cudaFuncSetAttribute(mmbf_kernel,
                         cudaFuncAttributeMaxDynamicSharedMemorySize, GS_BF);

    auto gemm_tf = [&](int M, int N, int K,
                       const float* Ap, int lda, const float2* Bp,
                       const float* bias, float* Cp, int ldc,
                       const float* res, int ldres, int act) {
        dim3 grid(N / 64, (M + 63) / 64, 2);
        mm3t_kernel<<<grid, 128, GSMEM>>>(M, N, K / 2, Ap, lda, Bp, DD, part);
        int total = (M * N) / 4;
        finish_kernel<<<(total + 255) / 256, 256>>>(M, N, part, bias, Cp, ldc,
                                                    res, ldres, act);
    };
    auto gemm_bf = [&](int M, int N, int K,
                       const float* Ap, int lda, const unsigned* Bfp,
                       const float* bias, float* Cp, int ldc,
                       const float* res, int ldres, int act) {
        dim3 grid(N / 64, (M + 63) / 64, 2);
        mmbf_kernel<<<grid, 128, GS_BF>>>(M, N, K / 2, Ap, lda, Bfp, part);
        int total = (M * N) / 4;
        finish_kernel<<<(total + 255) / 256, 256>>>(M, N, part, bias, Cp, ldc,
                                                    res, ldres, act);
    };

    // ---- setup ----
    prep_tf32<<<(TF32_TOT + 2 * DD + 255) / 256, 256>>>(W0, dW, Ws, agbg, agbs, biasGS);
    prep_frag<<<(FRAG_SITES + 255) / 256, 256>>>(Wb, agWg, agWs, agWp, uW, We, Fr);
    mask_build<<<(N0 * N0) / 256, 256>>>(A, bm);

    // ---- encoder / down path (tf32x3) ----
    gemm_tf(N0, DD, DD, Xin, DD, Ws + OFF_W0, b0, X0, DD, nullptr, 0, 1);
    gemm_tf(N0, DD, DD, X0, DD, Ws + OFF_DW0, db, X1d, DD, nullptr, 0, 1);

    gemv_score<<<(N0 + 7) / 8, 256>>>(N0, X1d, pW, pwb, pb, phi, h1, e, eh);
    agg_l0<<<N0, 128>>>(bm, e, eh, sc);
    topk_rank<<<(N0 + 255) / 256, 256>>>(sc, N0, KK0, idx0, vals0);
    pool_gather<<<(KK0 * DD + 255) / 256, 256>>>(X1d, idx0, vals0, KK0, X1);

    gemm_tf(KK0, DD, DD, X1, DD, Ws + OFF_DW1, db + DD, X2d, DD, nullptr, 0, 1);

    gemv_score<<<(KK0 + 7) / 8, 256>>>(KK0, X2d, pW + DD, pwb + 1, pb + 1, phi + 2, h1, e, eh);
    agg_l1<<<KK0, 256>>>(bm, idx0, KK0, e, eh, sc);
    topk_rank<<<(KK0 + 255) / 256, 256>>>(sc, KK0, KK1, idx1, vals1);
    pool_gather<<<(KK1 * DD + 255) / 256, 256>>>(X2d, idx1, vals1, KK1, X2);

    // ---- bottleneck + up path (bf16x3) ----
    gemm_bf(KK1, DD, DD, X2, DD, Fr + FB_WB, bb, Xb, DD, nullptr, 0, 1);

    inv_tag<<<(KK1 + 255) / 256, 256>>>(inv, idx1, KK1, 1);
    cat_fill<<<(KK0 * DD + 255) / 256, 256>>>(cat, inv, Xb, X2d, KK0, 1);
    gemm_bf(KK0, DD, DD2, cat, DD2, Fr + FB_CATW0, biasGS, G, DD, nullptr, 0, 1);
    gemm_bf(KK0, DD, DD,  G,   DD,  Fr + FB_AGP0, agbp, cat + DD, DD2, nullptr, 0, 2);
    gemm_bf(KK0, DD, DD2, cat, DD2, Fr + FB_UW0, ub, Xu1, DD, X2d, DD, 1);

    inv_tag<<<(KK0 + 255) / 256, 256>>>(inv, idx0, KK0, 2);
    cat_fill<<<(N0 * DD + 255) / 256, 256>>>(cat, inv, Xu1, X1d, N0, 2);
    gemm_bf(N0, DD, DD2, cat, DD2, Fr + FB_CATW1, biasGS + DD, G, DD, nullptr, 0, 1);
    gemm_bf(N0, DD, DD,  G,   DD,  Fr + FB_AGP1, agbp + DD, cat + DD, DD2, nullptr, 0, 2);
    gemm_bf(N0, DD, DD2, cat, DD2, Fr + FB_UW1, ub + DD, Xu0, DD, X1d, DD, 1);

    // ---- head ----
    head_fill<<<(N0 * DD + 255) / 256, 256>>>(cat, Xu0, X0, N0);
    gemm_bf(N0, DD, DD2, cat, DD2, Fr + FB_WE, be, (float*)d_out, DD, nullptr, 0, 1);

    if (out_size >= 2 * N0 * DD) {
        cudaMemcpyAsync((float*)d_out + (size_t)N0 * DD, X0,
                        (size_t)N0 * DD * sizeof(float), cudaMemcpyDeviceToDevice, 0);
    }
}

// round 16
// speedup vs baseline: 1.1376x; 1.1376x over previous
#include <cuda_runtime.h>
#include <cuda_bf16.h>
#include <math.h>

#define N0   4096
#define DD   320
#define DD2  640
#define KK0  3276
#define KK1  1965
#define NW   128

// ---- tf32 split-weight buffer (down-path only), float2 units ----
#define OFF_W0     0
#define OFF_DW0    102400
#define OFF_DW1    204800
#define TF32_TOT   307200

// ---- bf16 fragment buffer (up-path), uint32 units ----
#define FB_WB      0
#define FB_CATW0   102400
#define FB_CATW1   307200
#define FB_AGP0    512000
#define FB_AGP1    614400
#define FB_UW0     716800
#define FB_UW1     921600
#define FB_WE      1126400
#define FRAG_TOT   1331200
#define FRAG_SITES 665600

__device__ float2   s_Wsplit[TF32_TOT];
__device__ unsigned s_Wfrag [FRAG_TOT];
__device__ float    s_partial[2*N0*DD];
__device__ float    s_X0 [N0*DD];
__device__ float    s_X1d[N0*DD];
__device__ float    s_X2d[N0*DD];
__device__ float    s_Xb [N0*DD];
__device__ float    s_X1 [N0*DD];
__device__ float    s_X2 [N0*DD];
__device__ float    s_G  [N0*DD];
__device__ float    s_Xu1[N0*DD];
__device__ float    s_Xu0[N0*DD];
__device__ float    s_cat[N0*DD2];
__device__ unsigned s_bm [N0*NW];
__device__ float    s_h1 [N0];
__device__ float    s_e  [N0];
__device__ float    s_eh [N0];
__device__ float    s_sc [N0];
__device__ float    s_vals0[N0];
__device__ float    s_vals1[N0];
__device__ int      s_idx0[N0];
__device__ int      s_idx1[N0];
__device__ int      s_inv [N0];
__device__ float    s_biasGS[2*DD];

__device__ __forceinline__ unsigned cvt_tf32(float x) {
    unsigned r;
    asm("cvt.rna.tf32.f32 %0, %1;" : "=r"(r) : "f"(x));
    return r;
}
__device__ __forceinline__ float2 make_split(float x) {
    unsigned hi = cvt_tf32(x);
    float hf = __uint_as_float(hi);
    unsigned lo = cvt_tf32(x - hf);
    return make_float2(hf, __uint_as_float(lo));
}

__device__ __forceinline__ void mma8(float* d, const unsigned* a, const unsigned* b) {
    asm volatile(
        "mma.sync.aligned.m16n8k8.row.col.f32.tf32.tf32.f32 "
        "{%0,%1,%2,%3}, {%4,%5,%6,%7}, {%8,%9}, {%0,%1,%2,%3};"
        : "+f"(d[0]), "+f"(d[1]), "+f"(d[2]), "+f"(d[3])
        : "r"(a[0]), "r"(a[1]), "r"(a[2]), "r"(a[3]), "r"(b[0]), "r"(b[1]));
}

__device__ __forceinline__ void mma16(float* d, const unsigned* a, unsigned b0, unsigned b1) {
    asm volatile(
        "mma.sync.aligned.m16n8k16.row.col.f32.bf16.bf16.f32 "
        "{%0,%1,%2,%3}, {%4,%5,%6,%7}, {%8,%9}, {%0,%1,%2,%3};"
        : "+f"(d[0]), "+f"(d[1]), "+f"(d[2]), "+f"(d[3])
        : "r"(a[0]), "r"(a[1]), "r"(a[2]), "r"(a[3]), "r"(b0), "r"(b1));
}

__device__ __forceinline__ void cpa16(unsigned dst, const void* src, int nbytes) {
    asm volatile("cp.async.cg.shared.global [%0], [%1], 16, %2;"
                 :: "r"(dst), "l"(src), "r"(nbytes));
}

__device__ __forceinline__ unsigned split_bf2(float2 v, unsigned* lo) {
    __nv_bfloat162 h = __floats2bfloat162_rn(v.x, v.y);
    float2 hf = __bfloat1622float2(h);
    __nv_bfloat162 l = __floats2bfloat162_rn(v.x - hf.x, v.y - hf.y);
    *lo = *reinterpret_cast<unsigned*>(&l);
    return *reinterpret_cast<unsigned*>(&h);
}

// ---------------------------------------------------------------------------
// tf32 split + 64-col permutation (down-path weights) + fused bias sum tail
// ---------------------------------------------------------------------------
__global__ void prep_tf32(const float* __restrict__ W0,
                          const float* __restrict__ dW,
                          float2* __restrict__ out,
                          const float* __restrict__ bg,
                          const float* __restrict__ bs,
                          float* __restrict__ biasGS)
{
    int gid = blockIdx.x * blockDim.x + threadIdx.x;
    if (gid >= TF32_TOT) {
        int b = gid - TF32_TOT;
        if (b < 2 * DD) biasGS[b] = bg[b] + bs[b];
        return;
    }
    float x = (gid < 102400) ? W0[gid] : dW[gid - 102400];
    int col = gid % DD;
    int pcol = (col & ~63) | ((col & 7) << 3) | ((col >> 3) & 7);
    out[gid - col + pcol] = make_split(x);
}

// ---------------------------------------------------------------------------
// bf16 split + fragment-major packing (up-path weights)
// ---------------------------------------------------------------------------
__global__ void prep_frag(const float* __restrict__ Wb,
                          const float* __restrict__ agWg,
                          const float* __restrict__ agWs,
                          const float* __restrict__ agWp,
                          const float* __restrict__ uW,
                          const float* __restrict__ We,
                          unsigned* __restrict__ out)
{
    int gid = blockIdx.x * blockDim.x + threadIdx.x;
    if (gid >= FRAG_SITES) return;
    int s = gid;
    const float* src = nullptr;
    long fb = 0;
    int catL = -1;
    if (s < 51200)                    { src = Wb;             fb = FB_WB;    }
    else if ((s -= 51200) < 102400)   { catL = 0;             fb = FB_CATW0; }
    else if ((s -= 102400) < 102400)  { catL = 1;             fb = FB_CATW1; }
    else if ((s -= 102400) < 51200)   { src = agWp;           fb = FB_AGP0;  }
    else if ((s -= 51200) < 51200)    { src = agWp + 102400;  fb = FB_AGP1;  }
    else if ((s -= 51200) < 102400)   { src = uW;             fb = FB_UW0;   }
    else if ((s -= 102400) < 102400)  { src = uW + 204800;    fb = FB_UW1;   }
    else { s -= 102400;                 src = We;             fb = FB_WE;    }

    int block = s >> 9;
    int r = s & 511;
    int tg = r >> 7, g = (r >> 4) & 7, nt = (r >> 1) & 7, reg = r & 1;
    int kb = block / 5, cbi = block % 5;
    int k0 = kb * 16 + tg * 2 + reg * 8;
    int col = cbi * 64 + nt * 8 + g;
    float x0, x1;
    if (catL >= 0) {
        const float* g0 = agWg + catL * 102400;
        const float* s0 = agWs + catL * 102400;
        x0 = (k0 < 320) ? g0[k0 * 320 + col] : s0[(k0 - 320) * 320 + col];
        x1 = (k0 + 1 < 320) ? g0[(k0 + 1) * 320 + col] : s0[(k0 + 1 - 320) * 320 + col];
    } else {
        x0 = src[(size_t)k0 * 320 + col];
        x1 = src[(size_t)(k0 + 1) * 320 + col];
    }
    __nv_bfloat162 h = __floats2bfloat162_rn(x0, x1);
    float2 hf = __bfloat1622float2(h);
    __nv_bfloat162 l = __floats2bfloat162_rn(x0 - hf.x, x1 - hf.y);
    int q = nt * 2 + reg;
    int idx = (q >> 2) * 128 + (g * 4 + tg) * 4 + (q & 3);
    unsigned* blk = out + fb + (size_t)block * 1024;
    blk[idx]       = *reinterpret_cast<unsigned*>(&h);
    blk[512 + idx] = *reinterpret_cast<unsigned*>(&l);
}

__global__ void mask_build(const float* __restrict__ A, unsigned* __restrict__ bm) {
    int gid = blockIdx.x * blockDim.x + threadIdx.x;
    float v = A[gid];
    unsigned b = __ballot_sync(0xffffffffu, v != 0.0f);
    if ((threadIdx.x & 31) == 0) bm[gid >> 5] = b;
}

// ---------------------------------------------------------------------------
// tf32x3 GEMM (down path), 2-stage pipeline, split-K=2
// ---------------------------------------------------------------------------
#define AP_   36
#define BP_   66
#define GSMEM (2*64*AP_*4 + 2*32*BP_*8)

__global__ __launch_bounds__(128) void mm3t_kernel(
    int M, int N, int kslice,
    const float* __restrict__ A, int lda,
    const float2* __restrict__ B, int ldb,
    float* __restrict__ P)
{
    extern __shared__ float dsm[];
    float*  As = dsm;
    float2* Bs = (float2*)(dsm + 2 * 64 * AP_);

    const int tid  = threadIdx.x;
    const int wid  = tid >> 5;
    const int lane = tid & 31;
    const int g    = lane >> 2;
    const int tg   = lane & 3;

    const int row0  = blockIdx.y * 64;
    const int col0  = blockIdx.x * 64;
    const int kbase = blockIdx.z * kslice;
    const int rb    = wid * 16;

    unsigned aBase = (unsigned)__cvta_generic_to_shared(As);
    unsigned bBase = (unsigned)__cvta_generic_to_shared(Bs);

    float acc[8][4];
#pragma unroll
    for (int nt = 0; nt < 8; nt++) {
        acc[nt][0] = 0.f; acc[nt][1] = 0.f; acc[nt][2] = 0.f; acc[nt][3] = 0.f;
    }

    const int ktiles = kslice / 32;

    auto stage = [&](int kt, int s) {
        const int k0 = kbase + kt * 32;
#pragma unroll
        for (int i = 0; i < 4; i++) {
            int idx = i * 128 + tid;
            int r = idx >> 3, c4 = idx & 7;
            int gr = row0 + r;
            int nb = (gr < M) ? 16 : 0;
            int grc = gr < M ? gr : (M - 1);
            cpa16(aBase + (unsigned)(((s * 64 + r) * AP_ + c4 * 4) * 4),
                  A + (size_t)grc * lda + k0 + c4 * 4, nb);
        }
#pragma unroll
        for (int i = 0; i < 8; i++) {
            int idx = i * 128 + tid;
            int kr = idx >> 5, c2 = (idx & 31) * 2;
            cpa16(bBase + (unsigned)(((s * 32 + kr) * BP_ + c2) * 8),
                  B + (size_t)(k0 + kr) * ldb + col0 + c2, 16);
        }
        asm volatile("cp.async.commit_group;");
    };

    stage(0, 0);

    for (int kt = 0; kt < ktiles; kt++) {
        asm volatile("cp.async.wait_group 0;");
        __syncthreads();
        if (kt + 1 < ktiles) stage(kt + 1, (kt + 1) & 1);

        const int buf = kt & 1;
        const float*  Ab = As + buf * 64 * AP_;
        const float2* Bb = Bs + buf * 32 * BP_;

#pragma unroll
        for (int kk = 0; kk < 4; kk++) {
            const int kc = kk * 8;
            unsigned ahi[4], alo[4];
            {
                float x0 = Ab[(rb + g) * AP_ + kc + tg];
                float x1 = Ab[(rb + g + 8) * AP_ + kc + tg];
                float x2 = Ab[(rb + g) * AP_ + kc + tg + 4];
                float x3 = Ab[(rb + g + 8) * AP_ + kc + tg + 4];
                ahi[0] = cvt_tf32(x0); alo[0] = cvt_tf32(x0 - __uint_as_float(ahi[0]));
                ahi[1] = cvt_tf32(x1); alo[1] = cvt_tf32(x1 - __uint_as_float(ahi[1]));
                ahi[2] = cvt_tf32(x2); alo[2] = cvt_tf32(x2 - __uint_as_float(ahi[2]));
                ahi[3] = cvt_tf32(x3); alo[3] = cvt_tf32(x3 - __uint_as_float(ahi[3]));
            }
            const float4* rL = reinterpret_cast<const float4*>(Bb + (kc + tg) * BP_ + g * 8);
            const float4* rH = reinterpret_cast<const float4*>(Bb + (kc + tg + 4) * BP_ + g * 8);
            float4 Ls[4] = {rL[0], rL[1], rL[2], rL[3]};
            float4 Hs[4] = {rH[0], rH[1], rH[2], rH[3]};
#pragma unroll
            for (int nt = 0; nt < 8; nt++) {
                float4 l = Ls[nt >> 1], h = Hs[nt >> 1];
                float lx = (nt & 1) ? l.z : l.x;
                float ly = (nt & 1) ? l.w : l.y;
                float hx = (nt & 1) ? h.z : h.x;
                float hy = (nt & 1) ? h.w : h.y;
                unsigned bhi[2] = { __float_as_uint(lx), __float_as_uint(hx) };
                unsigned blo[2] = { __float_as_uint(ly), __float_as_uint(hy) };
                mma8(acc[nt], ahi, bhi);
                mma8(acc[nt], ahi, blo);
                mma8(acc[nt], alo, bhi);
            }
        }
        __syncthreads();
    }

    float* Pp = P + (size_t)blockIdx.z * M * N;
#pragma unroll
    for (int nt = 0; nt < 8; nt++) {
        const int col = col0 + nt * 8 + tg * 2;
#pragma unroll
        for (int h = 0; h < 2; h++) {
            const int r = row0 + rb + g + h * 8;
            if (r >= M) continue;
            *reinterpret_cast<float2*>(Pp + (size_t)r * N + col) =
                make_float2(acc[nt][h * 2 + 0], acc[nt][h * 2 + 1]);
        }
    }
}

// ---------------------------------------------------------------------------
// bf16x3 GEMM (up path), 3-stage pipeline.
// gridDim.z==1: fused epilogue (bias/act/res -> C). gridDim.z==2: raw partial.
// ---------------------------------------------------------------------------
#define GS_BF (3*64*AP_*4 + 3*2048*4)

__global__ __launch_bounds__(128) void mmbf_kernel(
    int M, int N, int kslice,
    const float* __restrict__ A, int lda,
    const unsigned* __restrict__ Bf,
    float* __restrict__ P,
    const float* __restrict__ bias,
    float* __restrict__ C, int ldc,
    const float* __restrict__ res, int ldres,
    int act)
{
    extern __shared__ float dsm[];
    float*    As = dsm;                              // [3][64][AP_]
    unsigned* Bs = (unsigned*)(dsm + 3 * 64 * AP_);  // [3][2048]

    const int tid  = threadIdx.x;
    const int wid  = tid >> 5;
    const int lane = tid & 31;
    const int g    = lane >> 2;
    const int tg   = lane & 3;

    const int row0  = blockIdx.y * 64;
    const int col0  = blockIdx.x * 64;
    const int kbase = blockIdx.z * kslice;
    const int rb    = wid * 16;

    unsigned aBase = (unsigned)__cvta_generic_to_shared(As);
    unsigned bBase = (unsigned)__cvta_generic_to_shared(Bs);

    float acc[8][4];
#pragma unroll
    for (int nt = 0; nt < 8; nt++) {
        acc[nt][0] = 0.f; acc[nt][1] = 0.f; acc[nt][2] = 0.f; acc[nt][3] = 0.f;
    }

    const int ktiles = kslice / 32;

    auto stage = [&](int kt, int s) {
        const int k0 = kbase + kt * 32;
#pragma unroll
        for (int i = 0; i < 4; i++) {
            int idx = i * 128 + tid;
            int r = idx >> 3, c4 = idx & 7;
            int gr = row0 + r;
            int nb = (gr < M) ? 16 : 0;
            int grc = gr < M ? gr : (M - 1);
            cpa16(aBase + (unsigned)(((s * 64 + r) * AP_ + c4 * 4) * 4),
                  A + (size_t)grc * lda + k0 + c4 * 4, nb);
        }
        const int kb0 = k0 >> 4;
#pragma unroll
        for (int i = 0; i < 4; i++) {
            int c = i * 128 + tid;
            int sub = c >> 8, i16 = c & 255;
            const unsigned* src = Bf + ((size_t)(kb0 + sub) * 5 + blockIdx.x) * 1024 + i16 * 4;
            cpa16(bBase + (unsigned)((s * 2048 + sub * 1024 + i16 * 4) * 4), src, 16);
        }
        asm volatile("cp.async.commit_group;");
    };

    stage(0, 0);
    if (ktiles > 1) stage(1, 1);

    for (int kt = 0; kt < ktiles; kt++) {
        if (kt + 2 <= ktiles) {
            asm volatile("cp.async.wait_group 1;");
        } else {
            asm volatile("cp.async.wait_group 0;");
        }
        __syncthreads();
        if (kt + 2 < ktiles) stage(kt + 2, (kt + 2) % 3);

        const int buf = kt % 3;
        const float* Ab = As + buf * 64 * AP_;

#pragma unroll
        for (int sub = 0; sub < 2; sub++) {
            const unsigned* Bb = Bs + buf * 2048 + sub * 1024;
            float2 p0 = *reinterpret_cast<const float2*>(&Ab[(rb + g) * AP_ + sub * 16 + tg * 2]);
            float2 p1 = *reinterpret_cast<const float2*>(&Ab[(rb + g + 8) * AP_ + sub * 16 + tg * 2]);
            float2 p2 = *reinterpret_cast<const float2*>(&Ab[(rb + g) * AP_ + sub * 16 + tg * 2 + 8]);
            float2 p3 = *reinterpret_cast<const float2*>(&Ab[(rb + g + 8) * AP_ + sub * 16 + tg * 2 + 8]);
            unsigned ahi[4], alo[4];
            ahi[0] = split_bf2(p0, &alo[0]);
            ahi[1] = split_bf2(p1, &alo[1]);
            ahi[2] = split_bf2(p2, &alo[2]);
            ahi[3] = split_bf2(p3, &alo[3]);
            const uint4* bh4 = reinterpret_cast<const uint4*>(Bb + lane * 4);
            const uint4* bl4 = reinterpret_cast<const uint4*>(Bb + 512 + lane * 4);
            uint4 bh[4], bl[4];
#pragma unroll
            for (int j = 0; j < 4; j++) { bh[j] = bh4[j * 32]; bl[j] = bl4[j * 32]; }
#pragma unroll
            for (int nt = 0; nt < 8; nt++) {
                uint4 h = bh[nt >> 1], l = bl[nt >> 1];
                unsigned h0 = (nt & 1) ? h.z : h.x;
                unsigned h1 = (nt & 1) ? h.w : h.y;
                unsigned l0 = (nt & 1) ? l.z : l.x;
                unsigned l1 = (nt & 1) ? l.w : l.y;
                mma16(acc[nt], ahi, h0, h1);
                mma16(acc[nt], ahi, l0, l1);
                mma16(acc[nt], alo, h0, h1);
            }
        }
        __syncthreads();
    }

    if (gridDim.z == 1) {
        // fused epilogue: C = act(acc + bias) (+res)
#pragma unroll
        for (int nt = 0; nt < 8; nt++) {
            const int col = col0 + nt * 8 + tg * 2;
            float b0 = bias[col], b1 = bias[col + 1];
#pragma unroll
            for (int h = 0; h < 2; h++) {
                const int r = row0 + rb + g + h * 8;
                if (r >= M) continue;
                float v0 = acc[nt][h * 2 + 0] + b0;
                float v1 = acc[nt][h * 2 + 1] + b1;
                if (act == 1) {
                    v0 = fmaxf(v0, 0.f); v1 = fmaxf(v1, 0.f);
                } else if (act == 2) {
                    v0 = 1.f / (1.f + expf(-v0));
                    v1 = 1.f / (1.f + expf(-v1));
                }
                if (res) {
                    const float2 rv = *reinterpret_cast<const float2*>(res + (size_t)r * ldres + col);
                    v0 += rv.x; v1 += rv.y;
                }
                *reinterpret_cast<float2*>(C + (size_t)r * ldc + col) = make_float2(v0, v1);
            }
        }
    } else {
        float* Pp = P + (size_t)blockIdx.z * M * N;
#pragma unroll
        for (int nt = 0; nt < 8; nt++) {
            const int col = col0 + nt * 8 + tg * 2;
#pragma unroll
            for (int h = 0; h < 2; h++) {
                const int r = row0 + rb + g + h * 8;
                if (r >= M) continue;
                *reinterpret_cast<float2*>(Pp + (size_t)r * N + col) =
                    make_float2(acc[nt][h * 2 + 0], acc[nt][h * 2 + 1]);
            }
        }
    }
}

// C = act(P0 + P1 + bias) (+res after act)
__global__ void finish_kernel(int M, int N,
                              const float* __restrict__ P,
                              const float* __restrict__ bias,
                              float* __restrict__ C, int ldc,
                              const float* __restrict__ res, int ldres,
                              int act)
{
    int gid = blockIdx.x * blockDim.x + threadIdx.x;
    int total = (M * N) >> 2;
    if (gid >= total) return;
    int nq = N >> 2;
    int r = gid / nq;
    int c = (gid - r * nq) << 2;

    float4 p0 = reinterpret_cast<const float4*>(P)[gid];
    float4 p1 = reinterpret_cast<const float4*>(P + (size_t)M * N)[gid];
    float4 bv = *reinterpret_cast<const float4*>(bias + c);
    float v0 = p0.x + p1.x + bv.x;
    float v1 = p0.y + p1.y + bv.y;
    float v2 = p0.z + p1.z + bv.z;
    float v3 = p0.w + p1.w + bv.w;
    if (act == 1) {
        v0 = fmaxf(v0, 0.f); v1 = fmaxf(v1, 0.f);
        v2 = fmaxf(v2, 0.f); v3 = fmaxf(v3, 0.f);
    } else if (act == 2) {
        v0 = 1.f / (1.f + expf(-v0)); v1 = 1.f / (1.f + expf(-v1));
        v2 = 1.f / (1.f + expf(-v2)); v3 = 1.f / (1.f + expf(-v3));
    }
    if (res) {
        const float4 rv = *reinterpret_cast<const float4*>(res + (size_t)r * ldres + c);
        v0 += rv.x; v1 += rv.y; v2 += rv.z; v3 += rv.w;
    }
    *reinterpret_cast<float4*>(C + (size_t)r * ldc + c) = make_float4(v0, v1, v2, v3);
}

__global__ void gemv_score(int M, const float* __restrict__ X,
                           const float* __restrict__ w,
                           const float* __restrict__ pwb,
                           const float* __restrict__ pb,
                           const float* __restrict__ phi0,
                           float* __restrict__ h1,
                           float* __restrict__ e, float* __restrict__ eh)
{
    int warp = (blockIdx.x * blockDim.x + threadIdx.x) >> 5;
    int lane = threadIdx.x & 31;
    if (warp >= M) return;
    const float* xr = X + (size_t)warp * DD;
    float s = 0.f;
    for (int k = lane; k < DD; k += 32) s += xr[k] * w[k];
#pragma unroll
    for (int o = 16; o > 0; o >>= 1) s += __shfl_down_sync(0xffffffffu, s, o);
    if (lane == 0) {
        float h = s + pwb[0] + pb[0];
        float ex = expf(phi0[0] * h);
        h1[warp] = h;
        e[warp] = ex;
        eh[warp] = ex * h;
    }
}

__global__ void agg_l0(const unsigned* __restrict__ bm,
                       const float* __restrict__ e,
                       const float* __restrict__ eh,
                       float* __restrict__ scores)
{
    int r = blockIdx.x;
    int t = threadIdx.x;
    unsigned w = bm[r * NW + t];
    if ((r >> 5) == t) w |= (1u << (r & 31));
    float se = 0.f, sh = 0.f;
    while (w) {
        int b = __ffs(w) - 1;
        w &= w - 1;
        int j = t * 32 + b;
        se += e[j];
        sh += eh[j];
    }
    __shared__ float r1[128], r2[128];
    r1[t] = se; r2[t] = sh;
    __syncthreads();
    for (int o = 64; o > 0; o >>= 1) {
        if (t < o) { r1[t] += r1[t + o]; r2[t] += r2[t + o]; }
        __syncthreads();
    }
    if (t == 0) {
        float agg = (r2[0] / r1[0]) * 0.01f;
        scores[r] = 1.f / (1.f + expf(-agg));
    }
}

__global__ void agg_l1(const unsigned* __restrict__ bm,
                       const int* __restrict__ idx0, int n1,
                       const float* __restrict__ e,
                       const float* __restrict__ eh,
                       float* __restrict__ scores)
{
    __shared__ unsigned rowbits[NW];
    int r = blockIdx.x;
    int t = threadIdx.x;
    int orig = idx0[r];
    if (t < NW) rowbits[t] = bm[orig * NW + t];
    __syncthreads();
    float se = 0.f, sh = 0.f;
    for (int j = t; j < n1; j += 256) {
        int c = idx0[j];
        bool in = (rowbits[c >> 5] >> (c & 31)) & 1u;
        if (j == r) in = true;
        if (in) { se += e[j]; sh += eh[j]; }
    }
    __shared__ float r1[256], r2[256];
    r1[t] = se; r2[t] = sh;
    __syncthreads();
    for (int o = 128; o > 0; o >>= 1) {
        if (t < o) { r1[t] += r1[t + o]; r2[t] += r2[t + o]; }
        __syncthreads();
    }
    if (t == 0) {
        float agg = (r2[0] / r1[0]) * 0.01f;
        scores[r] = 1.f / (1.f + expf(-agg));
    }
}

// 8 threads per row, 32 rows per block; exact same rank semantics as before.
__global__ void topk_rank(const float* __restrict__ s, int n, int kk,
                          int* __restrict__ idx, float* __restrict__ vals)
{
    __shared__ float buf[256];
    int li  = threadIdx.x >> 3;    // 0..31 local row
    int sub = threadIdx.x & 7;     // 0..7 sub-thread
    int i = blockIdx.x * 32 + li;
    float si = (i < n) ? s[i] : 0.f;
    int rank = 0;
    for (int base = 0; base < n; base += 256) {
        int j = base + threadIdx.x;
        buf[threadIdx.x] = (j < n) ? s[j] : -3.0e38f;
        __syncthreads();
        int lim = min(256, n - base);
        for (int t = sub; t < lim; t += 8) {
            float sj = buf[t];
            int j2 = base + t;
            if (sj > si || (sj == si && j2 < i)) rank++;
        }
        __syncthreads();
    }
#pragma unroll
    for (int o = 4; o > 0; o >>= 1)
        rank += __shfl_down_sync(0xffffffffu, rank, o, 8);
    if (sub == 0 && i < n && rank < kk) { idx[rank] = i; vals[rank] = si; }
}

__global__ void pool_gather(const float* __restrict__ src,
                            const int* __restrict__ idx,
                            const float* __restrict__ vals,
                            int rows, float* __restrict__ dst)
{
    int gid = blockIdx.x * blockDim.x + threadIdx.x;
    if (gid >= rows * DD) return;
    int r = gid / DD, c = gid % DD;
    dst[gid] = src[(size_t)idx[r] * DD + c] * vals[r];
}

__global__ void inv_tag(int* __restrict__ inv, const int* __restrict__ idx,
                        int kk, int tag) {
    int i = blockIdx.x * blockDim.x + threadIdx.x;
    if (i < kk) inv[idx[i]] = (tag << 24) | i;
}

__global__ void cat_fill(float* __restrict__ cat,
                         const int* __restrict__ inv,
                         const float* __restrict__ top,
                         const float* __restrict__ down, int rows, int tag)
{
    int gid = blockIdx.x * blockDim.x + threadIdx.x;
    if (gid >= rows * DD) return;
    int r = gid / DD, c = gid % DD;
    int iv = inv[r];
    bool valid = (iv >> 24) == tag;
    int top_r = iv & 0xFFFFFF;
    cat[(size_t)r * DD2 + c] = valid ? top[(size_t)top_r * DD + c] : 0.f;
    cat[(size_t)r * DD2 + DD + c] = down[gid];
}

__global__ void head_fill(float* __restrict__ cat,
                          const float* __restrict__ a,
                          const float* __restrict__ b, int rows)
{
    int gid = blockIdx.x * blockDim.x + threadIdx.x;
    if (gid >= rows * DD) return;
    int r = gid / DD, c = gid % DD;
    cat[(size_t)r * DD2 + c] = a[gid];
    cat[(size_t)r * DD2 + DD + c] = b[gid];
}

extern "C" void kernel_launch(void* const* d_in, const int* in_sizes, int n_in,
                              void* d_out, int out_size)
{
    const float* A     = (const float*)d_in[0];
    const float* Xin   = (const float*)d_in[1];
    const float* W0    = (const float*)d_in[2];
    const float* b0    = (const float*)d_in[3];
    const float* Wb    = (const float*)d_in[4];
    const float* bb    = (const float*)d_in[5];
    const float* We    = (const float*)d_in[6];
    const float* be    = (const float*)d_in[7];
    const float* dW    = (const float*)d_in[8];
    const float* db    = (const float*)d_in[9];
    const float* uW    = (const float*)d_in[10];
    const float* ub    = (const float*)d_in[11];
    const float* pW    = (const float*)d_in[12];
    const float* pwb   = (const float*)d_in[13];
    const float* pb    = (const float*)d_in[14];
    const float* phi   = (const float*)d_in[15];
    const float* agWg  = (const float*)d_in[16];
    const float* agbg  = (const float*)d_in[17];
    const float* agWs  = (const float*)d_in[18];
    const float* agbs  = (const float*)d_in[19];
    const float* agWp  = (const float*)d_in[20];
    const float* agbp  = (const float*)d_in[21];

    float *part, *X0, *X1d, *X2d, *Xb, *X1, *X2, *G, *Xu1, *Xu0, *cat;
    float *h1, *e, *eh, *sc, *vals0, *vals1, *biasGS;
    float2* Ws;
    unsigned *Fr, *bm;
    int *idx0, *idx1, *inv;
    cudaGetSymbolAddress((void**)&Ws,   s_Wsplit);
    cudaGetSymbolAddress((void**)&Fr,   s_Wfrag);
    cudaGetSymbolAddress((void**)&part, s_partial);
    cudaGetSymbolAddress((void**)&X0,  s_X0);
    cudaGetSymbolAddress((void**)&X1d, s_X1d);
    cudaGetSymbolAddress((void**)&X2d, s_X2d);
    cudaGetSymbolAddress((void**)&Xb,  s_Xb);
    cudaGetSymbolAddress((void**)&X1,  s_X1);
    cudaGetSymbolAddress((void**)&X2,  s_X2);
    cudaGetSymbolAddress((void**)&G,   s_G);
    cudaGetSymbolAddress((void**)&Xu1, s_Xu1);
    cudaGetSymbolAddress((void**)&Xu0, s_Xu0);
    cudaGetSymbolAddress((void**)&cat, s_cat);
    cudaGetSymbolAddress((void**)&bm,  s_bm);
    cudaGetSymbolAddress((void**)&h1,  s_h1);
    cudaGetSymbolAddress((void**)&e,   s_e);
    cudaGetSymbolAddress((void**)&eh,  s_eh);
    cudaGetSymbolAddress((void**)&sc,  s_sc);
    cudaGetSymbolAddress((void**)&vals0, s_vals0);
    cudaGetSymbolAddress((void**)&vals1, s_vals1);
    cudaGetSymbolAddress((void**)&idx0, s_idx0);
    cudaGetSymbolAddress((void**)&idx1, s_idx1);
    cudaGetSymbolAddress((void**)&inv,  s_inv);
    cudaGetSymbolAddress((void**)&biasGS, s_biasGS);

    cudaFuncSetAttribute(mm3t_kernel,
                         cudaFuncAttributeMaxDynamicSharedMemorySize, GSMEM);
    cudaFuncSetAttribute(mmbf_kernel,
                         cudaFuncAttributeMaxDynamicSharedMemorySize, GS_BF);

    auto gemm_tf = [&](int M, int N, int K,
                       const float* Ap, int lda, const float2* Bp,
                       const float* bias, float* Cp, int ldc,
                       const float* res, int ldres, int act) {
        dim3 grid(N / 64, (M + 63) / 64, 2);
        mm3t_kernel<<<grid, 128, GSMEM>>>(M, N, K / 2, Ap, lda, Bp, DD, part);
        int total = (M * N) / 4;
        finish_kernel<<<(total + 255) / 256, 256>>>(M, N, part, bias, Cp, ldc,
                                                    res, ldres, act);
    };
    auto gemm_bf = [&](int M, int N, int K,
                       const float* Ap, int lda, const unsigned* Bfp,
                       const float* bias, float* Cp, int ldc,
                       const float* res, int ldres, int act) {
        const bool split = (M < 2500);
        dim3 grid(N / 64, (M + 63) / 64, split ? 2 : 1);
        mmbf_kernel<<<grid, 128, GS_BF>>>(M, N, split ? K / 2 : K, Ap, lda, Bfp,
                                          part, bias, Cp, ldc, res, ldres, act);
        if (split) {
            int total = (M * N) / 4;
            finish_kernel<<<(total + 255) / 256, 256>>>(M, N, part, bias, Cp, ldc,
                                                        res, ldres, act);
        }
    };

    // ---- setup ----
    prep_tf32<<<(TF32_TOT + 2 * DD + 255) / 256, 256>>>(W0, dW, Ws, agbg, agbs, biasGS);
    prep_frag<<<(FRAG_SITES + 255) / 256, 256>>>(Wb, agWg, agWs, agWp, uW, We, Fr);
    mask_build<<<(N0 * N0) / 256, 256>>>(A, bm);

    // ---- encoder / down path (tf32x3, selection-exact) ----
    gemm_tf(N0, DD, DD, Xin, DD, Ws + OFF_W0, b0, X0, DD, nullptr, 0, 1);
    gemm_tf(N0, DD, DD, X0, DD, Ws + OFF_DW0, db, X1d, DD, nullptr, 0, 1);

    gemv_score<<<(N0 + 7) / 8, 256>>>(N0, X1d, pW, pwb, pb, phi, h1, e, eh);
    agg_l0<<<N0, 128>>>(bm, e, eh, sc);
    topk_rank<<<(N0 + 31) / 32, 256>>>(sc, N0, KK0, idx0, vals0);
    pool_gather<<<(KK0 * DD + 255) / 256, 256>>>(X1d, idx0, vals0, KK0, X1);

    gemm_tf(KK0, DD, DD, X1, DD, Ws + OFF_DW1, db + DD, X2d, DD, nullptr, 0, 1);

    gemv_score<<<(KK0 + 7) / 8, 256>>>(KK0, X2d, pW + DD, pwb + 1, pb + 1, phi + 2, h1, e, eh);
    agg_l1<<<KK0, 256>>>(bm, idx0, KK0, e, eh, sc);
    topk_rank<<<(KK0 + 31) / 32, 256>>>(sc, KK0, KK1, idx1, vals1);
    pool_gather<<<(KK1 * DD + 255) / 256, 256>>>(X2d, idx1, vals1, KK1, X2);

    // ---- bottleneck + up path (bf16x3) ----
    gemm_bf(KK1, DD, DD, X2, DD, Fr + FB_WB, bb, Xb, DD, nullptr, 0, 1);

    inv_tag<<<(KK1 + 255) / 256, 256>>>(inv, idx1, KK1, 1);
    cat_fill<<<(KK0 * DD + 255) / 256, 256>>>(cat, inv, Xb, X2d, KK0, 1);
    gemm_bf(KK0, DD, DD2, cat, DD2, Fr + FB_CATW0, biasGS, G, DD, nullptr, 0, 1);
    gemm_bf(KK0, DD, DD,  G,   DD,  Fr + FB_AGP0, agbp, cat + DD, DD2, nullptr, 0, 2);
    gemm_bf(KK0, DD, DD2, cat, DD2, Fr + FB_UW0, ub, Xu1, DD, X2d, DD, 1);

    inv_tag<<<(KK0 + 255) / 256, 256>>>(inv, idx0, KK0, 2);
    cat_fill<<<(N0 * DD + 255) / 256, 256>>>(cat, inv, Xu1, X1d, N0, 2);
    gemm_bf(N0, DD, DD2, cat, DD2, Fr + FB_CATW1, biasGS + DD, G, DD, nullptr, 0, 1);
    gemm_bf(N0, DD, DD,  G,   DD,  Fr + FB_AGP1, agbp + DD, cat + DD, DD2, nullptr, 0, 2);
    gemm_bf(N0, DD, DD2, cat, DD2, Fr + FB_UW1, ub + DD, Xu0, DD, X1d, DD, 1);

    // ---- head ----
    head_fill<<<(N0 * DD + 255) / 256, 256>>>(cat, Xu0, X0, N0);
    gemm_bf(N0, DD, DD2, cat, DD2, Fr + FB_WE, be, (float*)d_out, DD, nullptr, 0, 1);

    if (out_size >= 2 * N0 * DD) {
        cudaMemcpyAsync((float*)d_out + (size_t)N0 * DD, X0,
                        (size_t)N0 * DD * sizeof(float), cudaMemcpyDeviceToDevice, 0);
    }
}